// round 5
// baseline (speedup 1.0000x reference)
#include <cuda_runtime.h>

// SSIM loss, fused separable implementation with packed f32x2 math.
// pred, gt: f32 [16,3,512,512] -> out: f32 scalar = 1 - mean(ssim_map)
//
// (x,y) and (x^2,y^2) conv chains ride fma.rn.f32x2 (FFMA2: 2 FMAs per issue
// slot, only reachable via PTX); the xy chain stays scalar FFMA with an
// immediate multiplier (rt_SMSP=1 on sm_103a). Rows staged in smem as packed
// (x,y) pairs -> 11 LDS.64 per pixel instead of 22 LDS.32.

#define IMG_H 512
#define IMG_W 512
#define N_IMG 48            // B*C
#define TH 64               // output rows per block
#define NROWS (TH + 10)     // 74 input rows per strip
#define NITER 77            // 7*11: ring period 11 -> slot indices constant-fold
#define SPAD 8
#define SW (IMG_W + 2 * SPAD)
#define NSTRIPS (IMG_H / TH)   // 8
#define NBLK (N_IMG * NSTRIPS) // 384
#define C1F 0.0001f
#define C2F 0.0009f

#define GW0 0.00102838f
#define GW1 0.00759876f
#define GW2 0.03600078f
#define GW3 0.10936069f
#define GW4 0.21300553f
#define GW5 0.26601172f

__device__ float        g_partials[NBLK];
__device__ unsigned int g_count;          // zero-initialized; reset by last block

typedef unsigned long long u64;

static __device__ __forceinline__ u64 pack2(float lo, float hi) {
    u64 r; asm("mov.b64 %0, {%1, %2};" : "=l"(r) : "f"(lo), "f"(hi)); return r;
}
static __device__ __forceinline__ void unpack2(u64 v, float& lo, float& hi) {
    asm("mov.b64 {%0, %1}, %2;" : "=f"(lo), "=f"(hi) : "l"(v));
}
static __device__ __forceinline__ u64 fma2(u64 a, u64 b, u64 c) {
    u64 d; asm("fma.rn.f32x2 %0, %1, %2, %3;" : "=l"(d) : "l"(a), "l"(b), "l"(c)); return d;
}
static __device__ __forceinline__ u64 mul2(u64 a, u64 b) {
    u64 d; asm("mul.rn.f32x2 %0, %1, %2;" : "=l"(d) : "l"(a), "l"(b)); return d;
}

__global__ __launch_bounds__(512, 1)
void ssim_main(const float* __restrict__ pred, const float* __restrict__ gt,
               float* __restrict__ out)
{
    __shared__ u64   s2[2][SW];        // packed (x,y) rows, double buffered
    __shared__ float sred[16];
    __shared__ unsigned int s_last;

    // 6 distinct symmetric weights: scalar (immediates) + packed (register pairs)
    const float Wt[6] = {GW0, GW1, GW2, GW3, GW4, GW5};
    u64 W2[6];
    #pragma unroll
    for (int i = 0; i < 6; ++i) W2[i] = pack2(Wt[i], Wt[i]);

    const int c     = threadIdx.x;     // one thread per column
    const int strip = blockIdx.x;
    const int img   = blockIdx.y;
    const int bid   = img * NSTRIPS + strip;
    const int row0  = strip * TH;
    const float* px = pred + (size_t)img * (IMG_H * IMG_W);
    const float* py = gt   + (size_t)img * (IMG_H * IMG_W);

    if (c < SPAD) {                    // zero halo (stays zero all kernel)
        s2[0][c] = 0ULL; s2[1][c] = 0ULL;
        s2[0][SPAD + IMG_W + c] = 0ULL; s2[1][SPAD + IMG_W + c] = 0ULL;
    }

    // vertical ring: packed (mu1,mu2), packed (Exx,Eyy), scalar Exy
    u64 amu[11], avar[11]; float axy[11];
    #pragma unroll
    for (int j = 0; j < 11; ++j) { amu[j] = 0ULL; avar[j] = 0ULL; axy[j] = 0.f; }

    float xc = 0.f, yc = 0.f;
    {
        const int gr = row0 - 5;
        if ((unsigned)gr < IMG_H) { xc = px[gr * IMG_W + c]; yc = py[gr * IMG_W + c]; }
    }

    float tsum = 0.f;

    #pragma unroll 1
    for (int rb = 0; rb < NITER; rb += 11) {
        #pragma unroll
        for (int i = 0; i < 11; ++i) {          // rb%11==0 -> slots fold
            const int r = rb + i;
            const int b = r & 1;

            s2[b][SPAD + c] = pack2(xc, yc);
            __syncthreads();

            // prefetch next row under this row's compute
            float xn = 0.f, yn = 0.f;
            {
                const int gr = row0 - 5 + r + 1;
                if ((r + 1 < NROWS) && ((unsigned)gr < IMG_H)) {
                    xn = px[gr * IMG_W + c];
                    yn = py[gr * IMG_W + c];
                }
            }

            // horizontal 11-tap conv: packed mu / packed var, scalar xy
            u64 hmu = 0ULL, hvar = 0ULL; float hxy = 0.f;
            #pragma unroll
            for (int k = 0; k < 11; ++k) {
                const int wi = (k < 6) ? k : 10 - k;
                const u64 p = s2[b][SPAD - 5 + c + k];   // LDS.64 (x,y)
                hmu  = fma2(p, W2[wi], hmu);
                hvar = fma2(mul2(p, p), W2[wi], hvar);
                float pl, ph; unpack2(p, pl, ph);        // reg aliases, no-op
                hxy = fmaf(Wt[wi], pl * ph, hxy);        // FMUL + FFMA-imm
            }

            // vertical scatter into ring (indices constant-folded)
            #pragma unroll
            for (int j = 0; j < 11; ++j) {
                const int s  = (i + 1 + j) % 11;
                const int wi = (j < 6) ? j : 10 - j;
                amu[s]  = fma2(hmu,  W2[wi], amu[s]);
                avar[s] = fma2(hvar, W2[wi], avar[s]);
                axy[s]  = fmaf(Wt[wi], hxy, axy[s]);
            }

            // slot (i+1)%11 completed -> output row r-10
            const int s0 = (i + 1) % 11;
            const int o  = r - 10;
            if (o >= 0 && o < TH) {
                float mu1, mu2, Exx, Eyy;
                unpack2(amu[s0], mu1, mu2);
                unpack2(avar[s0], Exx, Eyy);
                const float m11 = mu1 * mu1;
                const float m22 = mu2 * mu2;
                const float m12 = mu1 * mu2;
                const float v1  = Exx - m11;
                const float v2  = Eyy - m22;
                const float v12 = axy[s0] - m12;
                const float num = (2.f * m12 + C1F) * (2.f * v12 + C2F);
                const float den = (m11 + m22 + C1F) * (v1 + v2 + C2F);
                tsum += __fdividef(num, den);
            }
            amu[s0] = 0ULL; avar[s0] = 0ULL; axy[s0] = 0.f;

            xc = xn; yc = yn;
        }
    }

    // deterministic block reduction
    #pragma unroll
    for (int off = 16; off > 0; off >>= 1)
        tsum += __shfl_down_sync(0xffffffffu, tsum, off);
    if ((c & 31) == 0) sred[c >> 5] = tsum;
    __syncthreads();
    if (c == 0) {
        float s = 0.f;
        #pragma unroll
        for (int w = 0; w < 16; ++w) s += sred[w];
        g_partials[bid] = s;
        __threadfence();
        const unsigned int old = atomicAdd(&g_count, 1u);
        s_last = (old == NBLK - 1) ? 1u : 0u;
    }
    __syncthreads();

    // last-finishing block reduces the 384 partials (fixed order -> deterministic)
    if (s_last) {
        float v = (c < NBLK) ? __ldcg(&g_partials[c]) : 0.f;
        #pragma unroll
        for (int off = 16; off > 0; off >>= 1)
            v += __shfl_down_sync(0xffffffffu, v, off);
        if ((c & 31) == 0) sred[c >> 5] = v;
        __syncthreads();
        if (c == 0) {
            float s = 0.f;
            #pragma unroll
            for (int w = 0; w < 16; ++w) s += sred[w];
            out[0] = 1.0f - s * (1.0f / 12582912.0f);
            g_count = 0;                       // re-arm for next graph replay
        }
    }
}

extern "C" void kernel_launch(void* const* d_in, const int* in_sizes, int n_in,
                              void* d_out, int out_size)
{
    (void)in_sizes; (void)n_in; (void)out_size;
    const float* pred = (const float*)d_in[0];
    const float* gt   = (const float*)d_in[1];

    dim3 grid(NSTRIPS, N_IMG);                 // (8, 48) = 384 blocks
    ssim_main<<<grid, IMG_W>>>(pred, gt, (float*)d_out);
}